// round 2
// baseline (speedup 1.0000x reference)
#include <cuda_runtime.h>
#include <cstdint>

// Fixed problem shape
#define NN      2048
#define NODES   4096                 // BATCH(2) * NN
#define FELEMS  8388608              // 2*2048*2048
#define GRID    296                  // 2 CTAs/SM * 148 SMs (co-resident, required for barriers)
#define TPB     512
#define LOG2E   1.4426950408889634f

// ---------------- device scratch ----------------
__device__ __align__(16) float g_d[FELEMS];       // (F1-F0)*log2e
__device__ __align__(16) float g_s1[2][NODES];    // double-buffered qS[...,1]
__device__ __align__(16) float g_c0[2][NODES];    // double-buffered qC[...,0]
__device__ __align__(16) float g_A[NODES];        // sum_y qF1 * s0[y]
__device__ __align__(16) float g_Bv[NODES];       // sum_x qF1 * s1[x]
__device__ unsigned g_bar[16];                    // barrier counters (reset by trailing kernel)

__device__ __forceinline__ float ex2f(float x) {
    float r; asm("ex2.approx.f32 %0, %1;" : "=f"(r) : "f"(x)); return r;
}

// 1/(1+u) for finite u>=0: magic-seed reciprocal + 2 Newton steps (rel err ~1.4e-6)
__device__ __forceinline__ float rcp1p(float u) {
    float den = 1.0f + u;
    float r = __uint_as_float(0x7ef311c3u - __float_as_uint(den));
    r = r * (2.0f - den * r);
    r = r * (2.0f - den * r);
    return r;
}

// sigmoid with clamp (args can be O(1000) in the node update)
__device__ __forceinline__ float sigmoid_safe(float z) {
    z = fminf(fmaxf(z, -30.0f), 30.0f);
    return rcp1p(ex2f(-z * LOG2E));
}

// device-wide barrier: REDG arrival + L2 spin; counters reset by reset_kernel
__device__ __forceinline__ void gbar(int idx) {
    __syncthreads();
    if (threadIdx.x == 0) {
        __threadfence();
        atomicAdd(&g_bar[idx], 1u);
        while (*((volatile unsigned*)&g_bar[idx]) < GRID) __nanosleep(32);
        __threadfence();
    }
    __syncthreads();
}

__global__ void __launch_bounds__(TPB, 2) logicmp_persistent(
    const float* __restrict__ S, const float* __restrict__ C,
    const float* __restrict__ F, const float* __restrict__ W,
    float* __restrict__ out)
{
    const int tid  = threadIdx.x;
    const int gtid = blockIdx.x * TPB + tid;
    const int gstr = GRID * TPB;

    // ---------------- phase 0: init + d = (F1-F0)*log2e ----------------
    for (int i = gtid; i < NODES; i += gstr) {
        float s1 = sigmoid_safe(S[2 * i + 1] - S[2 * i]);
        g_s1[0][i] = s1;
        g_s1[1][i] = s1;                       // prv slot for iter0 (unused: w1p=0, keep finite)
        g_c0[0][i] = sigmoid_safe(C[2 * i] - C[2 * i + 1]);
        g_Bv[i] = 0.0f;
    }
    {
        const float4* F4 = (const float4*)F;   // (F0,F1,F0,F1)
        float4* D4 = (float4*)g_d;
        for (int i = gtid; i < FELEMS / 4; i += gstr) {
            float4 fa = F4[2 * i], fb = F4[2 * i + 1];
            float4 dd;
            dd.x = (fa.y - fa.x) * LOG2E;
            dd.y = (fa.w - fa.z) * LOG2E;
            dd.z = (fb.y - fb.x) * LOG2E;
            dd.w = (fb.w - fb.z) * LOG2E;
            D4[i] = dd;
        }
    }
    const float w0 = W[0], w1 = W[1];
    gbar(0);

    // ---------------- 5 iterations ----------------
    __shared__ float sred[7][16];
    int bar = 1;
    const int colBase = tid * 4;
    const int lane = tid & 31, warp = tid >> 5;

    for (int k = 0; k < 5; k++) {
        const int cur = k & 1, prv = cur ^ 1;
        const float w1p2 = (k ? w1 : 0.0f) * LOG2E;

        for (int b = 0; b < 2; b++) {
            float4 cc = __ldcg((const float4*)&g_s1[cur][b * NN + colBase]);
            float4 cp = __ldcg((const float4*)&g_s1[prv][b * NN + colBase]);
            float s0c0 = 1.0f - cc.x, s0c1 = 1.0f - cc.y, s0c2 = 1.0f - cc.z, s0c3 = 1.0f - cc.w;
            float s0p0 = 1.0f - cp.x, s0p1 = 1.0f - cp.y, s0p2 = 1.0f - cp.z, s0p3 = 1.0f - cp.w;

            float col0 = 0.f, col1 = 0.f, col2 = 0.f, col3 = 0.f;
            float racc[7];
            int nr = 0;
            for (int r = blockIdx.x; r < NN; r += GRID) {
                const int row = b * NN + r;
                const float a2 = w1p2 * __ldcg(&g_s1[prv][row]);
                const float m  = __ldcg(&g_s1[cur][row]);
                const float4 d4 = *(const float4*)&g_d[row * NN + colBase];
                // qF1 = 1/(1 + 2^(a2*s0p - d'))
                float q0 = rcp1p(ex2f(fmaf(a2, s0p0, -d4.x)));
                float q1 = rcp1p(ex2f(fmaf(a2, s0p1, -d4.y)));
                float q2 = rcp1p(ex2f(fmaf(a2, s0p2, -d4.z)));
                float q3 = rcp1p(ex2f(fmaf(a2, s0p3, -d4.w)));
                racc[nr] = fmaf(q0, s0c0, fmaf(q1, s0c1, fmaf(q2, s0c2, q3 * s0c3)));
                col0 = fmaf(q0, m, col0);
                col1 = fmaf(q1, m, col1);
                col2 = fmaf(q2, m, col2);
                col3 = fmaf(q3, m, col3);
                nr++;
            }
            // row-sum reduction (A[row])
#pragma unroll
            for (int j = 0; j < 7; j++) {
                if (j < nr) {
                    float v = racc[j];
                    v += __shfl_down_sync(0xffffffffu, v, 16);
                    v += __shfl_down_sync(0xffffffffu, v, 8);
                    v += __shfl_down_sync(0xffffffffu, v, 4);
                    v += __shfl_down_sync(0xffffffffu, v, 2);
                    v += __shfl_down_sync(0xffffffffu, v, 1);
                    if (lane == 0) sred[j][warp] = v;
                }
            }
            __syncthreads();
            if (tid < 7) {
                const int r = blockIdx.x + tid * GRID;
                if (r < NN) {
                    float v = 0.0f;
#pragma unroll
                    for (int w = 0; w < 16; w++) v += sred[tid][w];
                    g_A[b * NN + r] = v;
                }
            }
            __syncthreads();
            // column partial sums (spread-address REDG)
            atomicAdd(&g_Bv[b * NN + colBase + 0], col0);
            atomicAdd(&g_Bv[b * NN + colBase + 1], col1);
            atomicAdd(&g_Bv[b * NN + colBase + 2], col2);
            atomicAdd(&g_Bv[b * NN + colBase + 3], col3);
        }
        gbar(bar++);

        if (k < 4) {
            if (blockIdx.x < 8) {          // node update: s1^{k+1}, c0^{k+1}, re-zero Bv
                const int i = blockIdx.x * TPB + tid;
                float Av  = __ldcg(&g_A[i]);
                float Bvv = __ldcg(&g_Bv[i]);
                float s1k = __ldcg(&g_s1[cur][i]);
                float c0k = __ldcg(&g_c0[cur][i]);
                float s1n = sigmoid_safe((S[2 * i + 1] + w1 * Bvv) -
                                         (S[2 * i] + w0 * c0k + w1 * Av));
                float c0n = sigmoid_safe(C[2 * i] - C[2 * i + 1] - w0 * s1k);
                g_s1[prv][i] = s1n;
                g_c0[prv][i] = c0n;
                g_Bv[i] = 0.0f;
            }
            gbar(bar++);
        }
    }

    // ---------------- final outputs ----------------
    // out layout: [S: 8192][C: 8192][F: 16777216] floats. s1^4 is in buffer 0.
    for (int r = blockIdx.x; r < NODES; r += GRID) {
        const int b = r >> 11;
        const float a = w1 * __ldcg(&g_s1[0][r]);
        const float4* Fr = (const float4*)(F + (size_t)r * (2 * NN));
        float4* Or = (float4*)(out + 16384 + (size_t)r * (2 * NN));
        const float* s1col = &g_s1[0][b * NN];
        for (int i = tid; i < NN / 2; i += TPB) {
            float4 f = Fr[i];
            float2 s = __ldcg((const float2*)&s1col[2 * i]);
            f.x = fmaf(a, 1.0f - s.x, f.x);
            f.z = fmaf(a, 1.0f - s.y, f.z);
            Or[i] = f;
        }
    }
    if (blockIdx.x >= GRID - 8) {
        const int i = (blockIdx.x - (GRID - 8)) * TPB + tid;
        float s1 = __ldcg(&g_s1[0][i]);
        out[2 * i]     = S[2 * i] + w0 * __ldcg(&g_c0[0][i]) + w1 * __ldcg(&g_A[i]);
        out[2 * i + 1] = S[2 * i + 1] + w1 * __ldcg(&g_Bv[i]);
        out[8192 + 2 * i]     = C[2 * i];
        out[8192 + 2 * i + 1] = C[2 * i + 1] + w0 * s1;
    }
}

// trailing reset so graph replays see zeroed barrier counters (runs after persistent kernel)
__global__ void reset_kernel() {
    if (threadIdx.x < 16) g_bar[threadIdx.x] = 0;
}

extern "C" void kernel_launch(void* const* d_in, const int* in_sizes, int n_in,
                              void* d_out, int out_size)
{
    const float* S = (const float*)d_in[0];
    const float* C = (const float*)d_in[1];
    const float* F = (const float*)d_in[2];
    const float* W = (const float*)d_in[3];
    float* out = (float*)d_out;

    logicmp_persistent<<<GRID, TPB>>>(S, C, F, W, out);
    reset_kernel<<<1, 32>>>();
}